// round 1
// baseline (speedup 1.0000x reference)
#include <cuda_runtime.h>
#include <math.h>

// Problem dims (fixed by setup_inputs)
#define B_   256
#define D_   256
#define D1   1024
#define D2   512
#define D3   256
#define NDIST (D1 + D2 + D3)   // 1792
#define KSEL 10

typedef unsigned long long ULL;

// ---------------- scratch (device globals; no cudaMalloc allowed) ----------
__device__ float g_z1[B_ * D1];
__device__ float g_h1[B_ * D1];
__device__ float g_m1[B_ * D1];
__device__ float g_z2[B_ * D2];
__device__ float g_h2[B_ * D2];
__device__ float g_m2[B_ * D2];
__device__ float g_z3[B_ * D3];
__device__ float g_V2[(size_t)B_ * D2 * D_];   // 128 MB
__device__ float g_V3[(size_t)B_ * D3 * D_];   //  64 MB
__device__ float g_dists[B_ * NDIST];
__device__ float g_partial[B_];

// ---------------- packed f32x2 helpers -------------------------------------
__device__ __forceinline__ ULL dup2(float x) {
    ULL r;
    asm("mov.b64 %0, {%1, %1};" : "=l"(r) : "f"(x));
    return r;
}
__device__ __forceinline__ void fma2(ULL& c, ULL a, ULL b) {
    asm("fma.rn.f32x2 %0, %1, %2, %0;" : "+l"(c) : "l"(a), "l"(b));
}

// ---------------- small forward-pass GEMM: Z = X @ W^T + bias --------------
// X [M,K] row-major, W [N,K] row-major. Optional relu H and 0/1 mask out.
__global__ __launch_bounds__(256) void zgemm_nt(
    const float* __restrict__ X, const float* __restrict__ W,
    const float* __restrict__ bias, int M, int N, int K,
    float* __restrict__ Z, float* __restrict__ H, float* __restrict__ Mk)
{
    const int BM = 64, BN = 64, BK = 16;
    __shared__ __align__(16) float Xs[BK][BM];
    __shared__ __align__(16) float Ws[BK][BN];

    int m0 = blockIdx.y * BM, n0 = blockIdx.x * BN;
    int tid = threadIdx.x;
    int tx = tid & 15, ty = tid >> 4;
    int lrow = tid >> 2, lcol = (tid & 3) * 4;   // 64 rows x 16 cols tile load

    float acc[4][4];
#pragma unroll
    for (int i = 0; i < 4; i++)
#pragma unroll
        for (int j = 0; j < 4; j++) acc[i][j] = 0.f;

    for (int k0 = 0; k0 < K; k0 += BK) {
        float4 xa = *(const float4*)(X + (size_t)(m0 + lrow) * K + k0 + lcol);
        float4 wa = *(const float4*)(W + (size_t)(n0 + lrow) * K + k0 + lcol);
        __syncthreads();
        Xs[lcol + 0][lrow] = xa.x; Xs[lcol + 1][lrow] = xa.y;
        Xs[lcol + 2][lrow] = xa.z; Xs[lcol + 3][lrow] = xa.w;
        Ws[lcol + 0][lrow] = wa.x; Ws[lcol + 1][lrow] = wa.y;
        Ws[lcol + 2][lrow] = wa.z; Ws[lcol + 3][lrow] = wa.w;
        __syncthreads();
#pragma unroll
        for (int k = 0; k < BK; k++) {
            float4 av = *(float4*)&Xs[k][ty * 4];
            float4 wv = *(float4*)&Ws[k][tx * 4];
            float a[4] = {av.x, av.y, av.z, av.w};
            float w[4] = {wv.x, wv.y, wv.z, wv.w};
#pragma unroll
            for (int i = 0; i < 4; i++)
#pragma unroll
                for (int j = 0; j < 4; j++) acc[i][j] += a[i] * w[j];
        }
    }

#pragma unroll
    for (int i = 0; i < 4; i++) {
        int m = m0 + ty * 4 + i;
#pragma unroll
        for (int j = 0; j < 4; j++) {
            int n = n0 + tx * 4 + j;
            float zv = acc[i][j] + bias[n];
            size_t o = (size_t)m * N + n;
            Z[o] = zv;
            if (H)  H[o]  = zv > 0.f ? zv : 0.f;
            if (Mk) Mk[o] = zv > 0.f ? 1.f : 0.f;
        }
    }
}

// ---------------- big batched masked GEMM ----------------------------------
// C[b] = (A ∘ mask[b]) @ Bm[b]
//   A    [M,K] row-major (shared across batch)
//   mask [B_,K] (0/1 floats), scales A columns
//   Bm   [K,N] row-major, per-batch base = Bm + b*bstride (bstride=0 → shared)
//   C    [B_,M,N]
// Tile: BM=128, BN=256, BK=8; 256 threads; 8x16 per-thread microtile via
// packed fma.rn.f32x2 (two N columns per accumulator).
__global__ __launch_bounds__(256, 1) void masked_gemm(
    const float* __restrict__ A, const float* __restrict__ mask,
    const float* __restrict__ Bm, size_t bstride,
    float* __restrict__ C, int M, int N, int K)
{
    const int BM = 128, BN = 256, BK = 8;
    __shared__ __align__(16) float As[2][BK][132];   // padded rows: STS conflict-free
    __shared__ __align__(16) float Bs[2][BK][BN];

    int b  = blockIdx.z;
    int m0 = blockIdx.y * BM;
    int n0 = blockIdx.x * BN;

    const float* mb = mask + (size_t)b * K;
    const float* Bb = Bm + (size_t)b * bstride;

    int tid = threadIdx.x;
    int tx = tid & 15, ty = tid >> 4;
    int arow = tid >> 1, acol = (tid & 1) * 4;       // A tile: 128 rows x 8 cols
    int brow = tid >> 6, bcol = (tid & 63) * 4;      // B tile: rows brow, brow+4

    ULL acc[8][8];
#pragma unroll
    for (int i = 0; i < 8; i++)
#pragma unroll
        for (int j = 0; j < 8; j++) acc[i][j] = 0ull;

    // preload k0 = 0
    {
        float4 a  = *(const float4*)(A  + (size_t)(m0 + arow) * K + acol);
        float4 mk = *(const float4*)(mb + acol);
        a.x *= mk.x; a.y *= mk.y; a.z *= mk.z; a.w *= mk.w;
        float4 b0 = *(const float4*)(Bb + (size_t)(brow)     * N + n0 + bcol);
        float4 b1 = *(const float4*)(Bb + (size_t)(brow + 4) * N + n0 + bcol);
        As[0][acol + 0][arow] = a.x; As[0][acol + 1][arow] = a.y;
        As[0][acol + 2][arow] = a.z; As[0][acol + 3][arow] = a.w;
        *(float4*)&Bs[0][brow][bcol]     = b0;
        *(float4*)&Bs[0][brow + 4][bcol] = b1;
    }
    __syncthreads();

    int cur = 0;
    for (int k0 = 0; k0 < K; k0 += BK) {
        int nk = k0 + BK;
        float4 na, nmk, nb0, nb1;
        if (nk < K) {
            na  = *(const float4*)(A  + (size_t)(m0 + arow) * K + nk + acol);
            nmk = *(const float4*)(mb + nk + acol);
            nb0 = *(const float4*)(Bb + (size_t)(nk + brow)     * N + n0 + bcol);
            nb1 = *(const float4*)(Bb + (size_t)(nk + brow + 4) * N + n0 + bcol);
        }
#pragma unroll
        for (int k = 0; k < BK; k++) {
            float4 a0 = *(float4*)&As[cur][k][ty * 8];
            float4 a1 = *(float4*)&As[cur][k][ty * 8 + 4];
            ULL bv[8];
#pragma unroll
            for (int jj = 0; jj < 4; jj++) {
                // thread's N-columns: tx*4 + jj*64 (strided → low bank conflicts)
                ulonglong2 t = *(ulonglong2*)&Bs[cur][k][tx * 4 + jj * 64];
                bv[2 * jj]     = t.x;
                bv[2 * jj + 1] = t.y;
            }
            float av[8] = {a0.x, a0.y, a0.z, a0.w, a1.x, a1.y, a1.z, a1.w};
#pragma unroll
            for (int i = 0; i < 8; i++) {
                ULL ad = dup2(av[i]);
#pragma unroll
                for (int j = 0; j < 8; j++) fma2(acc[i][j], ad, bv[j]);
            }
        }
        if (nk < K) {
            na.x *= nmk.x; na.y *= nmk.y; na.z *= nmk.z; na.w *= nmk.w;
            int nxt = cur ^ 1;
            As[nxt][acol + 0][arow] = na.x; As[nxt][acol + 1][arow] = na.y;
            As[nxt][acol + 2][arow] = na.z; As[nxt][acol + 3][arow] = na.w;
            *(float4*)&Bs[nxt][brow][bcol]     = nb0;
            *(float4*)&Bs[nxt][brow + 4][bcol] = nb1;
            __syncthreads();
            cur = nxt;
        }
    }

    float* Cb = C + (size_t)b * M * N;
#pragma unroll
    for (int i = 0; i < 8; i++) {
        size_t roff = (size_t)(m0 + ty * 8 + i) * N + n0;
#pragma unroll
        for (int jj = 0; jj < 4; jj++) {
            ulonglong2 v;
            v.x = acc[i][2 * jj];
            v.y = acc[i][2 * jj + 1];
            *(ulonglong2*)(Cb + roff + tx * 4 + jj * 64) = v;
        }
    }
}

// ---------------- distances: dist = |z| / ||V_row|| (row length = 256) -----
// V row base = V + b*vbs + r*256  (vbs=0 → shared across batch, e.g. W1)
__global__ void dist_kernel(const float* __restrict__ z, int zc,
                            const float* __restrict__ V, size_t vbs, int off)
{
    int warp = (blockIdx.x * blockDim.x + threadIdx.x) >> 5;
    int lane = threadIdx.x & 31;
    int total = B_ * zc;
    if (warp >= total) return;
    int b = warp / zc, r = warp % zc;
    const float4* vp = (const float4*)(V + (size_t)b * vbs + (size_t)r * 256);
    float4 v0 = vp[lane * 2];
    float4 v1 = vp[lane * 2 + 1];
    float s = v0.x * v0.x + v0.y * v0.y + v0.z * v0.z + v0.w * v0.w
            + v1.x * v1.x + v1.y * v1.y + v1.z * v1.z + v1.w * v1.w;
#pragma unroll
    for (int o = 16; o; o >>= 1) s += __shfl_xor_sync(0xffffffffu, s, o);
    if (lane == 0)
        g_dists[b * NDIST + off + r] = fabsf(z[(size_t)b * zc + r]) * rsqrtf(s);
}

// ---------------- per-batch smallest-k sum ----------------------------------
__global__ void topk_kernel()
{
    __shared__ float s[NDIST];
    __shared__ float rv[256];
    __shared__ int   ri[256];
    int b = blockIdx.x, t = threadIdx.x;
    for (int i = t; i < NDIST; i += 256) s[i] = g_dists[b * NDIST + i];
    __syncthreads();
    float tot = 0.f;
    for (int it = 0; it < KSEL; it++) {
        float best = 3.402823466e38f; int bi = NDIST;
        for (int i = t; i < NDIST; i += 256) {
            float v = s[i];
            if (v < best) { best = v; bi = i; }
        }
        rv[t] = best; ri[t] = bi;
        __syncthreads();
        for (int st = 128; st > 0; st >>= 1) {
            if (t < st) {
                if (rv[t + st] < rv[t] ||
                    (rv[t + st] == rv[t] && ri[t + st] < ri[t])) {
                    rv[t] = rv[t + st]; ri[t] = ri[t + st];
                }
            }
            __syncthreads();
        }
        if (t == 0) { tot += rv[0]; s[ri[0]] = 3.402823466e38f; }
        __syncthreads();
    }
    if (t == 0) g_partial[b] = tot;
}

__global__ void final_reduce(float* __restrict__ out)
{
    __shared__ float sh[256];
    int t = threadIdx.x;
    sh[t] = g_partial[t];
    __syncthreads();
    for (int st = 128; st > 0; st >>= 1) {
        if (t < st) sh[t] += sh[t + st];
        __syncthreads();
    }
    if (t == 0) out[0] = sh[0];
}

// ---------------- launch -----------------------------------------------------
extern "C" void kernel_launch(void* const* d_in, const int* in_sizes, int n_in,
                              void* d_out, int out_size)
{
    const float* x  = (const float*)d_in[0];
    const float* W1 = (const float*)d_in[1];
    const float* b1 = (const float*)d_in[2];
    const float* W2 = (const float*)d_in[3];
    const float* b2 = (const float*)d_in[4];
    const float* W3 = (const float*)d_in[5];
    const float* b3 = (const float*)d_in[6];
    float* out = (float*)d_out;

    float *z1p, *h1p, *m1p, *z2p, *h2p, *m2p, *z3p, *V2p, *V3p;
    cudaGetSymbolAddress((void**)&z1p, g_z1);
    cudaGetSymbolAddress((void**)&h1p, g_h1);
    cudaGetSymbolAddress((void**)&m1p, g_m1);
    cudaGetSymbolAddress((void**)&z2p, g_z2);
    cudaGetSymbolAddress((void**)&h2p, g_h2);
    cudaGetSymbolAddress((void**)&m2p, g_m2);
    cudaGetSymbolAddress((void**)&z3p, g_z3);
    cudaGetSymbolAddress((void**)&V2p, g_V2);
    cudaGetSymbolAddress((void**)&V3p, g_V3);

    // Forward pass (exact fp32 so masks match the reference)
    zgemm_nt<<<dim3(D1 / 64, B_ / 64), 256>>>(x,   W1, b1, B_, D1, D_,  z1p, h1p, m1p);
    zgemm_nt<<<dim3(D2 / 64, B_ / 64), 256>>>(h1p, W2, b2, B_, D2, D1, z2p, h2p, m2p);
    zgemm_nt<<<dim3(D3 / 64, B_ / 64), 256>>>(h2p, W3, b3, B_, D3, D2, z3p, (float*)0, (float*)0);

    // V2[b] = (W2 ∘ m1[b]) @ W1        [512 x 256] per batch
    masked_gemm<<<dim3(1, D2 / 128, B_), 256>>>(W2, m1p, W1, 0, V2p, D2, D_, D1);
    // V3[b] = (W3 ∘ m2[b]) @ V2[b]     [256 x 256] per batch
    masked_gemm<<<dim3(1, D3 / 128, B_), 256>>>(W3, m2p, V2p, (size_t)D2 * D_, V3p, D3, D_, D2);

    // distances
    {
        int rows1 = B_ * D1, rows2 = B_ * D2, rows3 = B_ * D3;
        dist_kernel<<<rows1 / 8, 256>>>(z1p, D1, W1, 0, 0);
        dist_kernel<<<rows2 / 8, 256>>>(z2p, D2, V2p, (size_t)D2 * D_, D1);
        dist_kernel<<<rows3 / 8, 256>>>(z3p, D3, V3p, (size_t)D3 * D_, D1 + D2);
    }

    // per-batch smallest-10 sums, then deterministic reduction
    topk_kernel<<<B_, 256>>>();
    final_reduce<<<1, 256>>>(out);
}